// round 16
// baseline (speedup 1.0000x reference)
#include <cuda_runtime.h>
#include <cuda_bf16.h>
#include <cstdint>
#include <math.h>

#define S_DIM 2048
#define B_DIM 32
#define H_DIM 1024
#define K_DIM 2048
#define M_DIM 65536

#define BM 128
#define BN 128
#define BKT 32
#define KTILES (K_DIM / BKT)     // 64
#define STAGES 3
#define THREADS 512              // 16 warps, 32x32 warp tiles
#define NTILES (H_DIM / BN)      // 8

// stage layout (bytes): Ah bf16 8K | Bh bf16 8K | qAh 4K | qAl 4K | qBh 4K | qBl 4K
#define PART_BH   8192
#define PART_Q    16384
#define STAGE_BYTES 32768
#define DSMEM_BYTES (STAGES * STAGE_BYTES)   // 96KB, 1 CTA/SM

// ---------------- device scratch ----------------
__device__ __nv_bfloat16 g_Ah[(size_t)M_DIM * K_DIM];   // 256MB
__device__ int8_t  g_qAh[(size_t)M_DIM * K_DIM];        // 128MB
__device__ int8_t  g_qAl[(size_t)M_DIM * K_DIM];        // 128MB
__device__ __nv_bfloat16 g_Bh[(size_t)H_DIM * K_DIM];
__device__ int8_t  g_qBh[(size_t)H_DIM * K_DIM];
__device__ int8_t  g_qBl[(size_t)H_DIM * K_DIM];
__device__ float g_sAh[M_DIM];                          // row scales (hi part)
__device__ float g_sAl[M_DIM];                          // row scales (lo part)
__device__ float g_sBh[H_DIM];
__device__ float g_sBl[H_DIM];
__device__ float g_hpart[8 * B_DIM * H_DIM];
__device__ float g_hprojT[H_DIM * B_DIM];               // [h][b]
__device__ float g_part[NTILES * M_DIM];

// ---------------- PTX helpers (baseline sm_80+ only) ----------------
__device__ __forceinline__ uint32_t smem_u32(const void* p) {
    uint32_t a;
    asm("{ .reg .u64 t; cvta.to.shared.u64 t, %1; cvt.u32.u64 %0, t; }" : "=r"(a) : "l"(p));
    return a;
}
__device__ __forceinline__ void cp16(uint32_t dst, const void* src) {
    asm volatile("cp.async.cg.shared.global [%0], [%1], 16;" :: "r"(dst), "l"(src) : "memory");
}
__device__ __forceinline__ void cp_commit() {
    asm volatile("cp.async.commit_group;" ::: "memory");
}
__device__ __forceinline__ void cp_wait1() {
    asm volatile("cp.async.wait_group 1;" ::: "memory");
}
__device__ __forceinline__ void ldsm4(uint32_t* r, uint32_t addr) {
    asm volatile("ldmatrix.sync.aligned.m8n8.x4.shared.b16 {%0,%1,%2,%3}, [%4];"
                 : "=r"(r[0]), "=r"(r[1]), "=r"(r[2]), "=r"(r[3]) : "r"(addr));
}
__device__ __forceinline__ void mma_bf16(float* c, const uint32_t* a, uint32_t b0, uint32_t b1) {
    asm volatile("mma.sync.aligned.m16n8k16.row.col.f32.bf16.bf16.f32 "
                 "{%0,%1,%2,%3}, {%4,%5,%6,%7}, {%8,%9}, {%0,%1,%2,%3};"
                 : "+f"(c[0]), "+f"(c[1]), "+f"(c[2]), "+f"(c[3])
                 : "r"(a[0]), "r"(a[1]), "r"(a[2]), "r"(a[3]), "r"(b0), "r"(b1));
}
__device__ __forceinline__ void mma_s8(int* c, const uint32_t* a, uint32_t b0, uint32_t b1) {
    asm volatile("mma.sync.aligned.m16n8k32.row.col.s32.s8.s8.s32 "
                 "{%0,%1,%2,%3}, {%4,%5,%6,%7}, {%8,%9}, {%0,%1,%2,%3};"
                 : "+r"(c[0]), "+r"(c[1]), "+r"(c[2]), "+r"(c[3])
                 : "r"(a[0]), "r"(a[1]), "r"(a[2]), "r"(a[3]), "r"(b0), "r"(b1));
}

// bf16 tile: 128 rows x 64B (4 chunks of 16B), conflict-free swizzle
__device__ __forceinline__ uint32_t tile_off(int row, int c) {
    return (uint32_t)(((row << 2) + (c ^ ((row >> 1) & 3))) << 4);
}
// int8 tile: 128 rows x 32B (2 chunks of 16B), conflict-free per 8-row ldsm phase
__device__ __forceinline__ uint32_t tile_off8(int row, int c) {
    return (uint32_t)(((row << 1) + (c ^ ((row >> 2) & 1))) << 4);
}

// ---------------------------------------------------------------------------
// prep: bprep (blocks [0,128): split+quantize+transpose We) + hproj1 ([128,384))
// ---------------------------------------------------------------------------
__global__ void prep_kernel(const float* __restrict__ W,
                            const float* __restrict__ hidden) {
    const int bid = blockIdx.x;
    const int t = threadIdx.x;
    const int wid = t >> 5, lane = t & 31;

    if (bid < 128) {
        // one warp per n-row
        const int n = bid * 8 + wid;
        float mh = 0.f, ml = 0.f;
        for (int i = 0; i < 64; i++) {
            int k = i * 32 + lane;
            float w = W[(size_t)(H_DIM + k) * H_DIM + n];
            float hf = __bfloat162float(__float2bfloat16_rn(w));
            mh = fmaxf(mh, fabsf(hf));
            ml = fmaxf(ml, fabsf(w - hf));
        }
#pragma unroll
        for (int o = 16; o > 0; o >>= 1) {
            mh = fmaxf(mh, __shfl_xor_sync(0xffffffffu, mh, o));
            ml = fmaxf(ml, __shfl_xor_sync(0xffffffffu, ml, o));
        }
        mh = fmaxf(mh, 1e-30f); ml = fmaxf(ml, 1e-30f);
        float invh = 127.f / mh, invl = 127.f / ml;
        if (lane == 0) { g_sBh[n] = mh / 127.f; g_sBl[n] = ml / 127.f; }
        for (int i = 0; i < 64; i++) {
            int k = i * 32 + lane;
            float w = W[(size_t)(H_DIM + k) * H_DIM + n];
            __nv_bfloat16 h = __float2bfloat16_rn(w);
            float hf = __bfloat162float(h);
            size_t o = (size_t)n * K_DIM + k;
            g_Bh[o] = h;
            g_qBh[o] = (int8_t)__float2int_rn(hf * invh);
            g_qBl[o] = (int8_t)__float2int_rn((w - hf) * invl);
        }
    } else {
        const int idx = bid - 128;         // 0..255
        const int b  = idx & 31;
        const int sl = idx >> 5;
        const int h4 = t * 4;
        if (t < 256) {
            const float* hr = hidden + b * H_DIM + sl * 128;
            float4 acc = make_float4(0.f, 0.f, 0.f, 0.f);
#pragma unroll 8
            for (int e = 0; e < 128; e++) {
                float f = hr[e];
                float4 w = *reinterpret_cast<const float4*>(
                    &W[(size_t)(sl * 128 + e) * H_DIM + h4]);
                acc.x += f * w.x; acc.y += f * w.y; acc.z += f * w.z; acc.w += f * w.w;
            }
            *reinterpret_cast<float4*>(&g_hpart[((size_t)sl * B_DIM + b) * H_DIM + h4]) = acc;
        }
    }
}

// ---------------------------------------------------------------------------
// hproj stage 2
// ---------------------------------------------------------------------------
__global__ void hproj2_kernel(const float* __restrict__ bias) {
    int g = blockIdx.x * 256 + threadIdx.x;
    int b = g >> 8;
    int h4 = (g & 255) * 4;
    float4 acc = make_float4(bias[h4], bias[h4 + 1], bias[h4 + 2], bias[h4 + 3]);
#pragma unroll
    for (int sl = 0; sl < 8; sl++) {
        float4 p = *reinterpret_cast<const float4*>(
            &g_hpart[((size_t)sl * B_DIM + b) * H_DIM + h4]);
        acc.x += p.x; acc.y += p.y; acc.z += p.z; acc.w += p.w;
    }
    g_hprojT[(h4 + 0) * B_DIM + b] = acc.x;
    g_hprojT[(h4 + 1) * B_DIM + b] = acc.y;
    g_hprojT[(h4 + 2) * B_DIM + b] = acc.z;
    g_hprojT[(h4 + 3) * B_DIM + b] = acc.w;
}

// ---------------------------------------------------------------------------
// aprep: one warp per m-row. Pass1: row maxes of |Ah|,|Al|; Pass2: write
// Ah bf16 + qAh,qAl int8 + scales.
// ---------------------------------------------------------------------------
__global__ void aprep_kernel(const float* __restrict__ enc) {
    const int wid = threadIdx.x >> 5, lane = threadIdx.x & 31;
    const size_t m = (size_t)blockIdx.x * 8 + wid;
    const float4* row = reinterpret_cast<const float4*>(enc + m * K_DIM);

    float mh = 0.f, ml = 0.f;
#pragma unroll 4
    for (int i = 0; i < 16; i++) {
        float4 f = row[i * 32 + lane];
        float x[4] = {f.x, f.y, f.z, f.w};
#pragma unroll
        for (int e = 0; e < 4; e++) {
            float hf = __bfloat162float(__float2bfloat16_rn(x[e]));
            mh = fmaxf(mh, fabsf(hf));
            ml = fmaxf(ml, fabsf(x[e] - hf));
        }
    }
#pragma unroll
    for (int o = 16; o > 0; o >>= 1) {
        mh = fmaxf(mh, __shfl_xor_sync(0xffffffffu, mh, o));
        ml = fmaxf(ml, __shfl_xor_sync(0xffffffffu, ml, o));
    }
    mh = fmaxf(mh, 1e-30f); ml = fmaxf(ml, 1e-30f);
    const float invh = 127.f / mh, invl = 127.f / ml;
    if (lane == 0) { g_sAh[m] = mh / 127.f; g_sAl[m] = ml / 127.f; }

#pragma unroll 4
    for (int i = 0; i < 16; i++) {
        float4 f = row[i * 32 + lane];
        float x[4] = {f.x, f.y, f.z, f.w};
        uint32_t hb[2];
        uint32_t qh = 0, ql = 0;
        float hfv[4];
#pragma unroll
        for (int e = 0; e < 4; e++) {
            __nv_bfloat16 h = __float2bfloat16_rn(x[e]);
            hfv[e] = __bfloat162float(h);
            uint16_t hu = *reinterpret_cast<uint16_t*>(&h);
            if (e < 2) hb[0] = (e == 0) ? hu : (hb[0] | ((uint32_t)hu << 16));
            else       hb[1] = (e == 2) ? hu : (hb[1] | ((uint32_t)hu << 16));
            int qhi = __float2int_rn(hfv[e] * invh);
            int qlo = __float2int_rn((x[e] - hfv[e]) * invl);
            qh |= ((uint32_t)(qhi & 255)) << (e * 8);
            ql |= ((uint32_t)(qlo & 255)) << (e * 8);
        }
        size_t k = (size_t)i * 128 + lane * 4;
        *reinterpret_cast<uint2*>(&g_Ah[m * K_DIM + k]) = make_uint2(hb[0], hb[1]);
        *reinterpret_cast<uint32_t*>(&g_qAh[m * K_DIM + k]) = qh;
        *reinterpret_cast<uint32_t*>(&g_qAl[m * K_DIM + k]) = ql;
    }
}

// ---------------------------------------------------------------------------
// GEMM: C = Ah·Bh (bf16) + sAh·sBl·(qAh·qBl) + sAl·sBh·(qAl·qBh), fused epilogue.
// grid (8 Ntiles, 512 Mtiles), 512 threads, 1 CTA/SM, 16 warps of 32x32.
// ---------------------------------------------------------------------------
__global__ __launch_bounds__(THREADS, 1)
void score_kernel(const float* __restrict__ v) {
    extern __shared__ char dsm[];
    const int tid  = threadIdx.x;
    const int wid  = tid >> 5;
    const int lane = tid & 31;
    const int Mo = blockIdx.y * BM;
    const int No = blockIdx.x * BN;

    const int wm = (wid & 3) * 32;     // warp M offset
    const int wn = (wid >> 2) * 32;    // warp N offset

    const int lrow = lane & 15, lk = lane >> 4;
    uint32_t aoff[2][2], boff[2][2];   // [mt][ks], [nb][ks]
    uint32_t aoff8[2], boff8[2];
#pragma unroll
    for (int ks = 0; ks < 2; ks++) {
#pragma unroll
        for (int mt = 0; mt < 2; mt++)
            aoff[mt][ks] = tile_off(wm + mt * 16 + lrow, ks * 2 + lk);
#pragma unroll
        for (int nb = 0; nb < 2; nb++)
            boff[nb][ks] = PART_BH + tile_off(wn + nb * 16 + lrow, ks * 2 + lk);
    }
#pragma unroll
    for (int mt = 0; mt < 2; mt++) aoff8[mt] = tile_off8(wm + mt * 16 + lrow, lk);
#pragma unroll
    for (int nb = 0; nb < 2; nb++) boff8[nb] = tile_off8(wn + nb * 16 + lrow, lk);

    // cp.async assignments
    const int rA = tid >> 2, cA = tid & 3;
    const uint32_t soA = tile_off(rA, cA);
    const uint32_t soB = PART_BH + soA;
    const char* pAh = reinterpret_cast<const char*>(&g_Ah[(size_t)(Mo + rA) * K_DIM + cA * 8]);
    const char* pBh = reinterpret_cast<const char*>(&g_Bh[(size_t)(No + rA) * K_DIM + cA * 8]);
    const char* p8[2];
    uint32_t so8[2];
#pragma unroll
    for (int s = 0; s < 2; s++) {
        int cid = tid + s * 512;
        int tq = cid >> 8;             // 0..3: qAh,qAl,qBh,qBl
        int rem = cid & 255;
        int r8 = rem >> 1, c8 = rem & 1;
        so8[s] = PART_Q + tq * 4096 + tile_off8(r8, c8);
        const int8_t* base =
            (tq == 0) ? &g_qAh[(size_t)(Mo + r8) * K_DIM + c8 * 16] :
            (tq == 1) ? &g_qAl[(size_t)(Mo + r8) * K_DIM + c8 * 16] :
            (tq == 2) ? &g_qBh[(size_t)(No + r8) * K_DIM + c8 * 16] :
                        &g_qBl[(size_t)(No + r8) * K_DIM + c8 * 16];
        p8[s] = reinterpret_cast<const char*>(base);
    }

    const uint32_t smb = smem_u32(dsm);
    float accf[2][4][4];
    int   acc1[2][4][4], acc2[2][4][4];
#pragma unroll
    for (int mt = 0; mt < 2; mt++)
#pragma unroll
        for (int j = 0; j < 4; j++)
#pragma unroll
            for (int e = 0; e < 4; e++) {
                accf[mt][j][e] = 0.f; acc1[mt][j][e] = 0; acc2[mt][j][e] = 0;
            }

    auto load_stage = [&](int slot) {
        uint32_t sb = smb + slot * STAGE_BYTES;
        cp16(sb + soA, pAh);
        cp16(sb + soB, pBh);
        cp16(sb + so8[0], p8[0]);
        cp16(sb + so8[1], p8[1]);
        pAh += 64; pBh += 64; p8[0] += 32; p8[1] += 32;
    };

    load_stage(0); cp_commit();
    load_stage(1); cp_commit();
    cp_wait1();
    __syncthreads();

    int slot_ld = 2, slot_cp = 0;
    for (int kt = 0; kt < KTILES; kt++) {
        if (kt + STAGES - 1 < KTILES) load_stage(slot_ld);
        cp_commit();
        if (++slot_ld == STAGES) slot_ld = 0;

        const uint32_t SB = smb + slot_cp * STAGE_BYTES;
        if (++slot_cp == STAGES) slot_cp = 0;
        const uint32_t QAH = SB + PART_Q, QAL = SB + PART_Q + 4096;
        const uint32_t QBH = SB + PART_Q + 8192, QBL = SB + PART_Q + 12288;

        // hi term (bf16, 2 k16 steps)
#pragma unroll
        for (int ks = 0; ks < 2; ks++) {
            uint32_t ah0[4], ah1[4];
            ldsm4(ah0, SB + aoff[0][ks]);
            ldsm4(ah1, SB + aoff[1][ks]);
#pragma unroll
            for (int nb = 0; nb < 2; nb++) {
                uint32_t bq[4];
                ldsm4(bq, SB + boff[nb][ks]);
                mma_bf16(accf[0][2 * nb],     ah0, bq[0], bq[2]);
                mma_bf16(accf[0][2 * nb + 1], ah0, bq[1], bq[3]);
                mma_bf16(accf[1][2 * nb],     ah1, bq[0], bq[2]);
                mma_bf16(accf[1][2 * nb + 1], ah1, bq[1], bq[3]);
            }
        }
        // corrections (int8, k32 in one step each)
        {
            uint32_t qa0[4], qa1[4];
            ldsm4(qa0, QAH + aoff8[0]);
            ldsm4(qa1, QAH + aoff8[1]);
#pragma unroll
            for (int nb = 0; nb < 2; nb++) {
                uint32_t qb[4];
                ldsm4(qb, QBL + boff8[nb]);
                mma_s8(acc1[0][2 * nb],     qa0, qb[0], qb[2]);
                mma_s8(acc1[0][2 * nb + 1], qa0, qb[1], qb[3]);
                mma_s8(acc1[1][2 * nb],     qa1, qb[0], qb[2]);
                mma_s8(acc1[1][2 * nb + 1], qa1, qb[1], qb[3]);
            }
            ldsm4(qa0, QAL + aoff8[0]);
            ldsm4(qa1, QAL + aoff8[1]);
#pragma unroll
            for (int nb = 0; nb < 2; nb++) {
                uint32_t qb[4];
                ldsm4(qb, QBH + boff8[nb]);
                mma_s8(acc2[0][2 * nb],     qa0, qb[0], qb[2]);
                mma_s8(acc2[0][2 * nb + 1], qa0, qb[1], qb[3]);
                mma_s8(acc2[1][2 * nb],     qa1, qb[0], qb[2]);
                mma_s8(acc2[1][2 * nb + 1], qa1, qb[1], qb[3]);
            }
        }
        cp_wait1();
        __syncthreads();
    }

    // ---- epilogue ----
    float* hp_s  = reinterpret_cast<float*>(dsm);               // [128][33]
    float* v_s   = hp_s + 128 * 33;                             // [128]
    float* sbl_s = v_s + 128;                                   // [128]
    float* sbh_s = sbl_s + 128;                                 // [128]
    float* red   = sbh_s + 128;                                 // [4][128]
    __syncthreads();
    for (int i = tid; i < 128 * 32; i += THREADS) {
        int nl = i >> 5, b = i & 31;
        hp_s[nl * 33 + b] = g_hprojT[(No + nl) * B_DIM + b];
    }
    if (tid < 128) {
        v_s[tid]   = v[No + tid];
        sbl_s[tid] = g_sBl[No + tid];
        sbh_s[tid] = g_sBh[No + tid];
    }
    __syncthreads();

#pragma unroll
    for (int mt = 0; mt < 2; mt++) {
        int rl0 = wm + mt * 16 + (lane >> 2);
        int r0 = Mo + rl0;
        float sah0 = g_sAh[r0],     sal0 = g_sAl[r0];
        float sah1 = g_sAh[r0 + 8], sal1 = g_sAl[r0 + 8];
        int b0r = r0 & 31, b1r = (r0 + 8) & 31;
        float s0 = 0.f, s1 = 0.f;
#pragma unroll
        for (int j = 0; j < 4; j++) {
            int nl = wn + j * 8 + (lane & 3) * 2;
            float sbl0 = sbl_s[nl], sbh0 = sbh_s[nl];
            float sbl1 = sbl_s[nl + 1], sbh1 = sbh_s[nl + 1];
            float c00 = accf[mt][j][0] + sah0 * sbl0 * (float)acc1[mt][j][0]
                                       + sal0 * sbh0 * (float)acc2[mt][j][0];
            float c01 = accf[mt][j][1] + sah0 * sbl1 * (float)acc1[mt][j][1]
                                       + sal0 * sbh1 * (float)acc2[mt][j][1];
            float c10 = accf[mt][j][2] + sah1 * sbl0 * (float)acc1[mt][j][2]
                                       + sal1 * sbh0 * (float)acc2[mt][j][2];
            float c11 = accf[mt][j][3] + sah1 * sbl1 * (float)acc1[mt][j][3]
                                       + sal1 * sbh1 * (float)acc2[mt][j][3];
            float vv0 = v_s[nl], vv1 = v_s[nl + 1];
            s0 += vv0 * tanhf(c00 + hp_s[nl * 33 + b0r]);
            s0 += vv1 * tanhf(c01 + hp_s[(nl + 1) * 33 + b0r]);
            s1 += vv0 * tanhf(c10 + hp_s[nl * 33 + b1r]);
            s1 += vv1 * tanhf(c11 + hp_s[(nl + 1) * 33 + b1r]);
        }
        s0 += __shfl_xor_sync(0xffffffffu, s0, 1);
        s0 += __shfl_xor_sync(0xffffffffu, s0, 2);
        s1 += __shfl_xor_sync(0xffffffffu, s1, 1);
        s1 += __shfl_xor_sync(0xffffffffu, s1, 2);
        if ((lane & 3) == 0) {
            red[(wid >> 2) * 128 + rl0] = s0;
            red[(wid >> 2) * 128 + rl0 + 8] = s1;
        }
    }
    __syncthreads();
    if (tid < 128)
        g_part[(size_t)blockIdx.x * M_DIM + Mo + tid] =
            red[tid] + red[128 + tid] + red[256 + tid] + red[384 + tid];
}

// ---------------------------------------------------------------------------
// softmax: sum 8 N-tile partials, softmax over S per batch row
// ---------------------------------------------------------------------------
__global__ void softmax_kernel(float* __restrict__ out) {
    __shared__ float srow[S_DIM];
    __shared__ float rd[256];
    const int b = blockIdx.x;
    const int t = threadIdx.x;

    float m = -INFINITY;
    for (int i = t; i < S_DIM; i += 256) {
        int mm = i * B_DIM + b;
        float sc = 0.f;
#pragma unroll
        for (int nt = 0; nt < NTILES; nt++) sc += g_part[(size_t)nt * M_DIM + mm];
        srow[i] = sc;
        m = fmaxf(m, sc);
    }
    rd[t] = m;
    __syncthreads();
    for (int o = 128; o > 0; o >>= 1) { if (t < o) rd[t] = fmaxf(rd[t], rd[t + o]); __syncthreads(); }
    m = rd[0];
    __syncthreads();

    float sum = 0.f;
    for (int i = t; i < S_DIM; i += 256) {
        float e = expf(srow[i] - m);
        srow[i] = e;
        sum += e;
    }
    rd[t] = sum;
    __syncthreads();
    for (int o = 128; o > 0; o >>= 1) { if (t < o) rd[t] += rd[t + o]; __syncthreads(); }
    float inv = 1.f / rd[0];
    __syncthreads();
    float* orow = out + (size_t)b * S_DIM;
    for (int i = t; i < S_DIM; i += 256) orow[i] = srow[i] * inv;
}

// ---------------------------------------------------------------------------
extern "C" void kernel_launch(void* const* d_in, const int* in_sizes, int n_in,
                              void* d_out, int out_size) {
    const float* hidden = (const float*)d_in[0];
    const float* enc    = (const float*)d_in[1];
    const float* W      = (const float*)d_in[2];
    const float* bias   = (const float*)d_in[3];
    const float* v      = (const float*)d_in[4];
    float* out = (float*)d_out;

    cudaFuncSetAttribute(score_kernel, cudaFuncAttributeMaxDynamicSharedMemorySize, DSMEM_BYTES);

    prep_kernel<<<384, 256>>>(W, hidden);                          // launch 0
    hproj2_kernel<<<32, 256>>>(bias);                              // launch 1
    aprep_kernel<<<M_DIM / 8, 256>>>(enc);                         // launch 2
    score_kernel<<<dim3(NTILES, M_DIM / BM), THREADS, DSMEM_BYTES>>>(v);  // launch 3 (profiled)
    softmax_kernel<<<B_DIM, 256>>>(out);                           // launch 4
}